// round 1
// baseline (speedup 1.0000x reference)
#include <cuda_runtime.h>
#include <math.h>

// ---------------------------------------------------------------------------
// Problem constants
//   F=128 frames, N=512 batch, MDL=512, HEADS=8, E=64, M(features)=128, HID=256
// ---------------------------------------------------------------------------
#define Fdim 128
#define Ndim 512
#define MDL  512
#define HEADS 8
#define Edim 64
#define Mfeat 128
#define HID 256
#define ROWS (Fdim * Ndim)          // 65536
#define QKV_STRIDE (3 * MDL)        // 1536
#define ROW_QKV ((size_t)Ndim * QKV_STRIDE)  // 512*1536 = 786432 per f-row

#define DN 0.35355339059327373f      // 64^-0.25
#define RATIO 0.08838834764831845f   // 128^-0.5
#define KEPS 1e-4f
#define ZEPS 1e-6f
#define LNEPS 1e-5f

// ---------------------------------------------------------------------------
// Scratch (device globals — no allocation allowed)
// ---------------------------------------------------------------------------
__device__ float g_qkv[(size_t)ROWS * QKV_STRIDE];          // 402 MB
__device__ float g_qf[(size_t)Ndim * HEADS * Fdim * Mfeat]; // 268 MB
__device__ float g_kf[(size_t)Ndim * HEADS * Fdim * Mfeat]; // 268 MB
__device__ float g_kv[(size_t)Ndim * HEADS * Edim * Mfeat]; // 134 MB
__device__ float g_ksum[(size_t)Ndim * HEADS * Mfeat];
__device__ float g_t[(size_t)ROWS * MDL];                   // attention out, [f,n,c]
__device__ float g_x1[(size_t)ROWS * MDL];                  // after addnorm1
__device__ float g_h1[(size_t)ROWS * HID];                  // ffn hidden
__device__ float g_y[(size_t)ROWS * MDL];                   // ffn out

// ---------------------------------------------------------------------------
// Generic SGEMM: C[M,N] = A[M,K] @ B[N,K]^T + bias[N], optional exact GELU.
// BM=BN=128, BK=8, 256 threads, 8x8 register tile. M%128==0, N%128==0, K%8==0.
// ---------------------------------------------------------------------------
__global__ void __launch_bounds__(256) sgemm128(
    const float* __restrict__ A, const float* __restrict__ B,
    const float* __restrict__ bias, float* __restrict__ C,
    int M, int N, int K, int act)
{
    __shared__ float As[8][128];
    __shared__ float Bs[8][128];
    const int tid = threadIdx.x;
    const int bm = blockIdx.y, bn = blockIdx.x;
    const float* Ag = A + (size_t)bm * 128 * K;
    const float* Bg = B + (size_t)bn * 128 * K;
    const int lrow = tid >> 1;
    const int lcol = (tid & 1) * 4;
    const int tr = (tid >> 4) * 8;
    const int tc = (tid & 15) * 8;

    float acc[8][8];
#pragma unroll
    for (int i = 0; i < 8; ++i)
#pragma unroll
        for (int j = 0; j < 8; ++j) acc[i][j] = 0.f;

    for (int k0 = 0; k0 < K; k0 += 8) {
        float4 av = *(const float4*)(Ag + (size_t)lrow * K + k0 + lcol);
        float4 bv = *(const float4*)(Bg + (size_t)lrow * K + k0 + lcol);
        As[lcol + 0][lrow] = av.x; As[lcol + 1][lrow] = av.y;
        As[lcol + 2][lrow] = av.z; As[lcol + 3][lrow] = av.w;
        Bs[lcol + 0][lrow] = bv.x; Bs[lcol + 1][lrow] = bv.y;
        Bs[lcol + 2][lrow] = bv.z; Bs[lcol + 3][lrow] = bv.w;
        __syncthreads();
#pragma unroll
        for (int k = 0; k < 8; ++k) {
            float ar[8], br[8];
            *(float4*)&ar[0] = *(const float4*)&As[k][tr];
            *(float4*)&ar[4] = *(const float4*)&As[k][tr + 4];
            *(float4*)&br[0] = *(const float4*)&Bs[k][tc];
            *(float4*)&br[4] = *(const float4*)&Bs[k][tc + 4];
#pragma unroll
            for (int i = 0; i < 8; ++i)
#pragma unroll
                for (int j = 0; j < 8; ++j)
                    acc[i][j] += ar[i] * br[j];
        }
        __syncthreads();
    }

    float* Cg = C + (size_t)(bm * 128 + tr) * N + bn * 128 + tc;
#pragma unroll
    for (int i = 0; i < 8; ++i) {
#pragma unroll
        for (int jj = 0; jj < 2; ++jj) {
            float4 o;
            float* po = (float*)&o;
#pragma unroll
            for (int j = 0; j < 4; ++j) {
                float v = acc[i][jj * 4 + j] + bias[bn * 128 + tc + jj * 4 + j];
                if (act) v = 0.5f * v * (1.0f + erff(v * 0.7071067811865476f));
                po[j] = v;
            }
            *(float4*)(Cg + (size_t)i * N + jj * 4) = o;
        }
    }
}

// ---------------------------------------------------------------------------
// FAVOR+ feature map: per (sel, n, h) block computes
//   qf/kf[l, m] = ratio * (exp(dn * (data @ proj^T) - diag - rowmax) + keps)
// data[l=128, e=64] gathered from g_qkv; proj[m=128, e=64].
// 256 threads, each thread owns an 8x8 tile of the 128x128 output.
// ---------------------------------------------------------------------------
__global__ void __launch_bounds__(256) feature_k(const float* __restrict__ proj)
{
    extern __shared__ float sm[];
    float* sdata  = sm;                 // 128 x 65 (padded)
    float* sprojT = sm + 128 * 65;      // 64 x 128 (e-major)

    const int bx = blockIdx.x;
    const int sel = bx >> 12;           // 0 = q, 1 = k
    const int rem = bx & 4095;
    const int n = rem >> 3, h = rem & 7;
    const int tid = threadIdx.x;

    const size_t off0 = (size_t)n * QKV_STRIDE + (size_t)sel * MDL + (size_t)h * Edim;
    for (int idx = tid; idx < Fdim * Edim; idx += 256) {
        int l = idx >> 6, e = idx & 63;
        sdata[l * 65 + e] = g_qkv[(size_t)l * ROW_QKV + off0 + e];
    }
    for (int idx = tid; idx < Mfeat * Edim; idx += 256) {
        int m = idx >> 6, e = idx & 63;
        sprojT[e * 128 + m] = proj[idx];
    }
    __syncthreads();

    const int ty = tid >> 4, tx = tid & 15;
    float acc[8][8];
    float dsum[8];
#pragma unroll
    for (int i = 0; i < 8; ++i) {
        dsum[i] = 0.f;
#pragma unroll
        for (int j = 0; j < 8; ++j) acc[i][j] = 0.f;
    }

    for (int e = 0; e < 64; ++e) {
        float br[8];
        *(float4*)&br[0] = *(const float4*)&sprojT[e * 128 + tx * 8];
        *(float4*)&br[4] = *(const float4*)&sprojT[e * 128 + tx * 8 + 4];
#pragma unroll
        for (int i = 0; i < 8; ++i) {
            float a = sdata[(ty * 8 + i) * 65 + e];
            dsum[i] += a * a;
#pragma unroll
            for (int j = 0; j < 8; ++j) acc[i][j] += a * br[j];
        }
    }

    float* out = (sel ? g_kf : g_qf) + (size_t)(n * 8 + h) * (Fdim * Mfeat);
#pragma unroll
    for (int i = 0; i < 8; ++i) {
        float rm = -1e30f;
#pragma unroll
        for (int j = 0; j < 8; ++j) rm = fmaxf(rm, acc[i][j]);
        // reduce max across the 16 tx threads (same 16-lane shfl group)
#pragma unroll
        for (int o = 1; o < 16; o <<= 1)
            rm = fmaxf(rm, __shfl_xor_sync(0xffffffffu, rm, o));
        float stab = rm * DN;
        float diag = dsum[i] * (0.5f * DN * DN);
        float c = -diag - stab;
        int l = ty * 8 + i;
        float4 o0, o1;
        float* p0 = (float*)&o0; float* p1 = (float*)&o1;
#pragma unroll
        for (int j = 0; j < 4; ++j) {
            p0[j] = RATIO * (expf(acc[i][j] * DN + c) + KEPS);
            p1[j] = RATIO * (expf(acc[i][4 + j] * DN + c) + KEPS);
        }
        *(float4*)&out[l * 128 + tx * 8]     = o0;
        *(float4*)&out[l * 128 + tx * 8 + 4] = o1;
    }
}

// ---------------------------------------------------------------------------
// kv[e,m] = sum_s v[s,e] * kf[s,m]   and   ksum[m] = sum_s kf[s,m]
// One block per (n,h). 256 threads, each owns 8(e) x 4(m) outputs.
// ---------------------------------------------------------------------------
__global__ void __launch_bounds__(256) kv_k()
{
    extern __shared__ float sm[];
    float* vsm = sm;              // 128 x 65 (padded)  v[s][e]
    float* kfs = sm + 128 * 65;   // 128 x 128          kf[s][m]

    const int bx = blockIdx.x;    // n*8 + h
    const int n = bx >> 3, h = bx & 7;
    const int tid = threadIdx.x;

    const size_t voff = (size_t)n * QKV_STRIDE + 2 * MDL + (size_t)h * Edim;
    for (int idx = tid; idx < Fdim * Edim; idx += 256) {
        int s = idx >> 6, e = idx & 63;
        vsm[s * 65 + e] = g_qkv[(size_t)s * ROW_QKV + voff + e];
    }
    const float* kfg = g_kf + (size_t)bx * (Fdim * Mfeat);
    for (int idx = tid; idx < Fdim * Mfeat; idx += 256) kfs[idx] = kfg[idx];
    __syncthreads();

    const int ty = tid >> 5, tx = tid & 31;
    float acc[8][4];
#pragma unroll
    for (int i = 0; i < 8; ++i)
#pragma unroll
        for (int j = 0; j < 4; ++j) acc[i][j] = 0.f;

    for (int s = 0; s < 128; ++s) {
        float br[4];
        *(float4*)br = *(const float4*)&kfs[s * 128 + tx * 4];
#pragma unroll
        for (int i = 0; i < 8; ++i) {
            float a = vsm[s * 65 + ty * 8 + i];
#pragma unroll
            for (int j = 0; j < 4; ++j) acc[i][j] += a * br[j];
        }
    }

    float* kvo = g_kv + (size_t)bx * (Edim * Mfeat);
#pragma unroll
    for (int i = 0; i < 8; ++i) {
        int e = ty * 8 + i;
        float4 o = { acc[i][0], acc[i][1], acc[i][2], acc[i][3] };
        *(float4*)&kvo[e * 128 + tx * 4] = o;
    }

    if (tid < 128) {
        float s = 0.f;
        for (int sidx = 0; sidx < 128; ++sidx) s += kfs[sidx * 128 + tid];
        g_ksum[(size_t)bx * 128 + tid] = s;
    }
}

// ---------------------------------------------------------------------------
// t[l,e] = (sum_m qf[l,m]*kv[e,m]) / (sum_m qf[l,m]*ksum[m] + eps)
// One block per (n,h). Output scattered into [f, n, h*64+e] layout.
// ---------------------------------------------------------------------------
__global__ void __launch_bounds__(256) attn_k()
{
    extern __shared__ float sm[];
    float* qfs = sm;                    // 128 x 129 (padded)
    float* kvT = sm + 128 * 129;        // 128(m) x 64(e)
    float* ks  = kvT + 128 * 64;        // 128

    const int bx = blockIdx.x;
    const int n = bx >> 3, h = bx & 7;
    const int tid = threadIdx.x;

    const float* qfg = g_qf + (size_t)bx * (Fdim * Mfeat);
    for (int idx = tid; idx < Fdim * Mfeat; idx += 256) {
        int l = idx >> 7, m = idx & 127;
        qfs[l * 129 + m] = qfg[idx];
    }
    const float* kvg = g_kv + (size_t)bx * (Edim * Mfeat);
    for (int idx = tid; idx < Edim * Mfeat; idx += 256) {
        int e = idx >> 7, m = idx & 127;
        kvT[m * 64 + e] = kvg[idx];
    }
    if (tid < 128) ks[tid] = g_ksum[(size_t)bx * 128 + tid];
    __syncthreads();

    const int ty = tid >> 4, tx = tid & 15;
    float acc[8][4];
    float den[8];
#pragma unroll
    for (int i = 0; i < 8; ++i) {
        den[i] = 0.f;
#pragma unroll
        for (int j = 0; j < 4; ++j) acc[i][j] = 0.f;
    }

    for (int m = 0; m < 128; ++m) {
        float br[4];
        *(float4*)br = *(const float4*)&kvT[m * 64 + tx * 4];
        float km = ks[m];
#pragma unroll
        for (int i = 0; i < 8; ++i) {
            float a = qfs[(ty * 8 + i) * 129 + m];
            den[i] += a * km;
#pragma unroll
            for (int j = 0; j < 4; ++j) acc[i][j] += a * br[j];
        }
    }

#pragma unroll
    for (int i = 0; i < 8; ++i) {
        int l = ty * 8 + i;
        float inv = 1.0f / (den[i] + ZEPS);
        float4 o = { acc[i][0] * inv, acc[i][1] * inv, acc[i][2] * inv, acc[i][3] * inv };
        *(float4*)&g_t[((size_t)l * Ndim + n) * MDL + h * Edim + tx * 4] = o;
    }
}

// ---------------------------------------------------------------------------
// out = LayerNorm(a + res) * g + b   per row of 512. One block per row.
// ---------------------------------------------------------------------------
__global__ void __launch_bounds__(128) addnorm_k(
    const float* __restrict__ a, const float* __restrict__ res,
    const float* __restrict__ g, const float* __restrict__ b,
    float* __restrict__ out)
{
    __shared__ float red[8];
    const int r = blockIdx.x, tid = threadIdx.x;
    const size_t base = (size_t)r * MDL + tid * 4;

    float4 va = *(const float4*)(a + base);
    float4 vr = *(const float4*)(res + base);
    float v[4] = { va.x + vr.x, va.y + vr.y, va.z + vr.z, va.w + vr.w };

    float s  = v[0] + v[1] + v[2] + v[3];
    float s2 = v[0]*v[0] + v[1]*v[1] + v[2]*v[2] + v[3]*v[3];
#pragma unroll
    for (int o = 16; o > 0; o >>= 1) {
        s  += __shfl_xor_sync(0xffffffffu, s,  o);
        s2 += __shfl_xor_sync(0xffffffffu, s2, o);
    }
    if ((tid & 31) == 0) { red[tid >> 5] = s; red[4 + (tid >> 5)] = s2; }
    __syncthreads();
    float ts  = red[0] + red[1] + red[2] + red[3];
    float ts2 = red[4] + red[5] + red[6] + red[7];
    float mean = ts * (1.0f / MDL);
    float var  = ts2 * (1.0f / MDL) - mean * mean;
    float rstd = rsqrtf(var + LNEPS);

    float4 gg = *(const float4*)(g + tid * 4);
    float4 bb = *(const float4*)(b + tid * 4);
    float4 o;
    o.x = (v[0] - mean) * rstd * gg.x + bb.x;
    o.y = (v[1] - mean) * rstd * gg.y + bb.y;
    o.z = (v[2] - mean) * rstd * gg.z + bb.z;
    o.w = (v[3] - mean) * rstd * gg.w + bb.w;
    *(float4*)(out + base) = o;
}

// ---------------------------------------------------------------------------
// Host launcher
// ---------------------------------------------------------------------------
extern "C" void kernel_launch(void* const* d_in, const int* in_sizes, int n_in,
                              void* d_out, int out_size)
{
    const float* x     = (const float*)d_in[0];
    const float* w_qkv = (const float*)d_in[1];
    const float* b_qkv = (const float*)d_in[2];
    const float* proj  = (const float*)d_in[3];
    const float* ln1_g = (const float*)d_in[4];
    const float* ln1_b = (const float*)d_in[5];
    const float* ln2_g = (const float*)d_in[6];
    const float* ln2_b = (const float*)d_in[7];
    const float* w1    = (const float*)d_in[8];
    const float* b1    = (const float*)d_in[9];
    const float* w2    = (const float*)d_in[10];
    const float* b2    = (const float*)d_in[11];
    float* out = (float*)d_out;

    float *p_qkv, *p_t, *p_x1, *p_h1, *p_y;
    cudaGetSymbolAddress((void**)&p_qkv, g_qkv);
    cudaGetSymbolAddress((void**)&p_t,   g_t);
    cudaGetSymbolAddress((void**)&p_x1,  g_x1);
    cudaGetSymbolAddress((void**)&p_h1,  g_h1);
    cudaGetSymbolAddress((void**)&p_y,   g_y);

    const int feat_smem = (128 * 65 + 64 * 128) * 4;            // 66048
    const int kv_smem   = (128 * 65 + 128 * 128) * 4;           // 98816
    const int attn_smem = (128 * 129 + 128 * 64 + 128) * 4;     // 99328
    cudaFuncSetAttribute(feature_k, cudaFuncAttributeMaxDynamicSharedMemorySize, feat_smem);
    cudaFuncSetAttribute(kv_k,      cudaFuncAttributeMaxDynamicSharedMemorySize, kv_smem);
    cudaFuncSetAttribute(attn_k,    cudaFuncAttributeMaxDynamicSharedMemorySize, attn_smem);

    // 1) qkv = x @ w_qkv^T + b_qkv          [65536,1536]
    sgemm128<<<dim3(QKV_STRIDE / 128, ROWS / 128), 256>>>(
        x, w_qkv, b_qkv, p_qkv, ROWS, QKV_STRIDE, MDL, 0);

    // 2) FAVOR+ feature maps for q and k    (8192 (sel,n,h) tiles)
    feature_k<<<2 * Ndim * HEADS, 256, feat_smem>>>(proj);

    // 3) kv + ksum per (n,h)
    kv_k<<<Ndim * HEADS, 256, kv_smem>>>();

    // 4) attention output t (incl. 1/z), scattered to [f,n,c]
    attn_k<<<Ndim * HEADS, 256, attn_smem>>>();

    // 5) x1 = LN(t + x)
    addnorm_k<<<ROWS, 128>>>(p_t, x, ln1_g, ln1_b, p_x1);

    // 6) h1 = gelu(x1 @ w1^T + b1)          [65536,256]
    sgemm128<<<dim3(HID / 128, ROWS / 128), 256>>>(
        p_x1, w1, b1, p_h1, ROWS, HID, MDL, 1);

    // 7) y = h1 @ w2^T + b2                  [65536,512]
    sgemm128<<<dim3(MDL / 128, ROWS / 128), 256>>>(
        p_h1, w2, b2, p_y, ROWS, MDL, HID, 0);

    // 8) out = LN(y + x1)
    addnorm_k<<<ROWS, 128>>>(p_y, p_x1, ln2_g, ln2_b, out);
}

// round 2
// speedup vs baseline: 1.8209x; 1.8209x over previous
#include <cuda_runtime.h>
#include <math.h>
#include <stdint.h>

// ---------------------------------------------------------------------------
// Problem constants
// ---------------------------------------------------------------------------
#define Fdim 128
#define Ndim 512
#define MDL  512
#define HEADS 8
#define Edim 64
#define Mfeat 128
#define HID 256
#define ROWS (Fdim * Ndim)          // 65536
#define QKV_STRIDE (3 * MDL)        // 1536
#define ROW_QKV ((size_t)Ndim * QKV_STRIDE)

#define DN 0.35355339059327373f      // 64^-0.25
#define RATIO 0.08838834764831845f   // 128^-0.5
#define KEPS 1e-4f
#define ZEPS 1e-6f
#define LNEPS 1e-5f

// ---------------------------------------------------------------------------
// Scratch (device globals — no allocation allowed)
// ---------------------------------------------------------------------------
__device__ float g_qkv[(size_t)ROWS * QKV_STRIDE];
__device__ float g_qf[(size_t)Ndim * HEADS * Fdim * Mfeat];
__device__ float g_kf[(size_t)Ndim * HEADS * Fdim * Mfeat];
__device__ float g_kv[(size_t)Ndim * HEADS * Edim * Mfeat];
__device__ float g_ksum[(size_t)Ndim * HEADS * Mfeat];
__device__ float g_t[(size_t)ROWS * MDL];
__device__ float g_x1[(size_t)ROWS * MDL];
__device__ float g_h1[(size_t)ROWS * HID];
__device__ float g_y[(size_t)ROWS * MDL];

// ---------------------------------------------------------------------------
// tf32 tensor-core GEMM: C[M,N] = A[M,K] @ B[N,K]^T + bias[N], optional GELU.
// BM=BN=128, BK=32, 256 threads (8 warps, 2x4), warp tile 64x32 via
// mma.sync.aligned.m16n8k8.row.col.f32.tf32.tf32.f32.
// Requires M%128==0, N%128==0, K%32==0.
// ---------------------------------------------------------------------------
__device__ __forceinline__ uint32_t f2tf32(float f) {
    uint32_t u;
    asm("cvt.rna.tf32.f32 %0, %1;" : "=r"(u) : "f"(f));
    return u;
}

__global__ void __launch_bounds__(256) tf32gemm(
    const float* __restrict__ A, const float* __restrict__ B,
    const float* __restrict__ bias, float* __restrict__ C,
    int M, int N, int K, int act)
{
    __shared__ uint32_t As[128][36];
    __shared__ uint32_t Bs[128][36];

    const int tid  = threadIdx.x;
    const int lane = tid & 31;
    const int w    = tid >> 5;
    const int warp_m = w & 1;    // 0..1  (64 rows each)
    const int warp_n = w >> 1;   // 0..3  (32 cols each)
    const int gid = lane >> 2;   // group id 0..7
    const int tig = lane & 3;    // thread-in-group 0..3

    const int bm = blockIdx.y, bn = blockIdx.x;
    const float* Ag = A + (size_t)bm * 128 * K;
    const float* Bg = B + (size_t)bn * 128 * K;

    // loader coords: each thread: 4 rows (stride 32), 4 consecutive cols
    const int lr = tid >> 3;        // 0..31
    const int lc = (tid & 7) * 4;   // 0..28

    float acc[4][4][4];
#pragma unroll
    for (int mt = 0; mt < 4; ++mt)
#pragma unroll
        for (int nt = 0; nt < 4; ++nt)
#pragma unroll
            for (int r = 0; r < 4; ++r) acc[mt][nt][r] = 0.f;

    for (int k0 = 0; k0 < K; k0 += 32) {
#pragma unroll
        for (int p = 0; p < 4; ++p) {
            int row = lr + p * 32;
            float4 av = *(const float4*)(Ag + (size_t)row * K + k0 + lc);
            float4 bv = *(const float4*)(Bg + (size_t)row * K + k0 + lc);
            As[row][lc + 0] = f2tf32(av.x); As[row][lc + 1] = f2tf32(av.y);
            As[row][lc + 2] = f2tf32(av.z); As[row][lc + 3] = f2tf32(av.w);
            Bs[row][lc + 0] = f2tf32(bv.x); Bs[row][lc + 1] = f2tf32(bv.y);
            Bs[row][lc + 2] = f2tf32(bv.z); Bs[row][lc + 3] = f2tf32(bv.w);
        }
        __syncthreads();

#pragma unroll
        for (int kk = 0; kk < 32; kk += 8) {
            uint32_t a[4][4], b[4][2];
#pragma unroll
            for (int mt = 0; mt < 4; ++mt) {
                int ar = warp_m * 64 + mt * 16 + gid;
                a[mt][0] = As[ar][kk + tig];
                a[mt][1] = As[ar + 8][kk + tig];
                a[mt][2] = As[ar][kk + tig + 4];
                a[mt][3] = As[ar + 8][kk + tig + 4];
            }
#pragma unroll
            for (int nt = 0; nt < 4; ++nt) {
                int br = warp_n * 32 + nt * 8 + gid;
                b[nt][0] = Bs[br][kk + tig];
                b[nt][1] = Bs[br][kk + tig + 4];
            }
#pragma unroll
            for (int mt = 0; mt < 4; ++mt)
#pragma unroll
                for (int nt = 0; nt < 4; ++nt) {
                    asm volatile(
                        "mma.sync.aligned.m16n8k8.row.col.f32.tf32.tf32.f32 "
                        "{%0,%1,%2,%3}, {%4,%5,%6,%7}, {%8,%9}, {%0,%1,%2,%3};"
                        : "+f"(acc[mt][nt][0]), "+f"(acc[mt][nt][1]),
                          "+f"(acc[mt][nt][2]), "+f"(acc[mt][nt][3])
                        : "r"(a[mt][0]), "r"(a[mt][1]), "r"(a[mt][2]), "r"(a[mt][3]),
                          "r"(b[nt][0]), "r"(b[nt][1]));
                }
        }
        __syncthreads();
    }

    // Epilogue: bias + optional exact GELU
#pragma unroll
    for (int mt = 0; mt < 4; ++mt) {
        int row = bm * 128 + warp_m * 64 + mt * 16 + gid;
#pragma unroll
        for (int nt = 0; nt < 4; ++nt) {
            int col = bn * 128 + warp_n * 32 + nt * 8 + 2 * tig;
            float b0 = bias[col], b1 = bias[col + 1];
            float v0 = acc[mt][nt][0] + b0;
            float v1 = acc[mt][nt][1] + b1;
            float v2 = acc[mt][nt][2] + b0;
            float v3 = acc[mt][nt][3] + b1;
            if (act) {
                v0 = 0.5f * v0 * (1.0f + erff(v0 * 0.7071067811865476f));
                v1 = 0.5f * v1 * (1.0f + erff(v1 * 0.7071067811865476f));
                v2 = 0.5f * v2 * (1.0f + erff(v2 * 0.7071067811865476f));
                v3 = 0.5f * v3 * (1.0f + erff(v3 * 0.7071067811865476f));
            }
            *(float2*)(C + (size_t)row * N + col)       = make_float2(v0, v1);
            *(float2*)(C + (size_t)(row + 8) * N + col) = make_float2(v2, v3);
        }
    }
}

// ---------------------------------------------------------------------------
// FAVOR+ feature map (unchanged from R0)
// ---------------------------------------------------------------------------
__global__ void __launch_bounds__(256) feature_k(const float* __restrict__ proj)
{
    extern __shared__ float sm[];
    float* sdata  = sm;                 // 128 x 65
    float* sprojT = sm + 128 * 65;      // 64 x 128

    const int bx = blockIdx.x;
    const int sel = bx >> 12;
    const int rem = bx & 4095;
    const int n = rem >> 3, h = rem & 7;
    const int tid = threadIdx.x;

    const size_t off0 = (size_t)n * QKV_STRIDE + (size_t)sel * MDL + (size_t)h * Edim;
    for (int idx = tid; idx < Fdim * Edim; idx += 256) {
        int l = idx >> 6, e = idx & 63;
        sdata[l * 65 + e] = g_qkv[(size_t)l * ROW_QKV + off0 + e];
    }
    for (int idx = tid; idx < Mfeat * Edim; idx += 256) {
        int m = idx >> 6, e = idx & 63;
        sprojT[e * 128 + m] = proj[idx];
    }
    __syncthreads();

    const int ty = tid >> 4, tx = tid & 15;
    float acc[8][8];
    float dsum[8];
#pragma unroll
    for (int i = 0; i < 8; ++i) {
        dsum[i] = 0.f;
#pragma unroll
        for (int j = 0; j < 8; ++j) acc[i][j] = 0.f;
    }

    for (int e = 0; e < 64; ++e) {
        float br[8];
        *(float4*)&br[0] = *(const float4*)&sprojT[e * 128 + tx * 8];
        *(float4*)&br[4] = *(const float4*)&sprojT[e * 128 + tx * 8 + 4];
#pragma unroll
        for (int i = 0; i < 8; ++i) {
            float a = sdata[(ty * 8 + i) * 65 + e];
            dsum[i] += a * a;
#pragma unroll
            for (int j = 0; j < 8; ++j) acc[i][j] += a * br[j];
        }
    }

    float* out = (sel ? g_kf : g_qf) + (size_t)(n * 8 + h) * (Fdim * Mfeat);
#pragma unroll
    for (int i = 0; i < 8; ++i) {
        float rm = -1e30f;
#pragma unroll
        for (int j = 0; j < 8; ++j) rm = fmaxf(rm, acc[i][j]);
#pragma unroll
        for (int o = 1; o < 16; o <<= 1)
            rm = fmaxf(rm, __shfl_xor_sync(0xffffffffu, rm, o));
        float stab = rm * DN;
        float diag = dsum[i] * (0.5f * DN * DN);
        float c = -diag - stab;
        int l = ty * 8 + i;
        float4 o0, o1;
        float* p0 = (float*)&o0; float* p1 = (float*)&o1;
#pragma unroll
        for (int j = 0; j < 4; ++j) {
            p0[j] = RATIO * (expf(acc[i][j] * DN + c) + KEPS);
            p1[j] = RATIO * (expf(acc[i][4 + j] * DN + c) + KEPS);
        }
        *(float4*)&out[l * 128 + tx * 8]     = o0;
        *(float4*)&out[l * 128 + tx * 8 + 4] = o1;
    }
}

// ---------------------------------------------------------------------------
// kv + ksum (unchanged)
// ---------------------------------------------------------------------------
__global__ void __launch_bounds__(256) kv_k()
{
    extern __shared__ float sm[];
    float* vsm = sm;
    float* kfs = sm + 128 * 65;

    const int bx = blockIdx.x;
    const int n = bx >> 3, h = bx & 7;
    const int tid = threadIdx.x;

    const size_t voff = (size_t)n * QKV_STRIDE + 2 * MDL + (size_t)h * Edim;
    for (int idx = tid; idx < Fdim * Edim; idx += 256) {
        int s = idx >> 6, e = idx & 63;
        vsm[s * 65 + e] = g_qkv[(size_t)s * ROW_QKV + voff + e];
    }
    const float* kfg = g_kf + (size_t)bx * (Fdim * Mfeat);
    for (int idx = tid; idx < Fdim * Mfeat; idx += 256) kfs[idx] = kfg[idx];
    __syncthreads();

    const int ty = tid >> 5, tx = tid & 31;
    float acc[8][4];
#pragma unroll
    for (int i = 0; i < 8; ++i)
#pragma unroll
        for (int j = 0; j < 4; ++j) acc[i][j] = 0.f;

    for (int s = 0; s < 128; ++s) {
        float br[4];
        *(float4*)br = *(const float4*)&kfs[s * 128 + tx * 4];
#pragma unroll
        for (int i = 0; i < 8; ++i) {
            float a = vsm[s * 65 + ty * 8 + i];
#pragma unroll
            for (int j = 0; j < 4; ++j) acc[i][j] += a * br[j];
        }
    }

    float* kvo = g_kv + (size_t)bx * (Edim * Mfeat);
#pragma unroll
    for (int i = 0; i < 8; ++i) {
        int e = ty * 8 + i;
        float4 o = { acc[i][0], acc[i][1], acc[i][2], acc[i][3] };
        *(float4*)&kvo[e * 128 + tx * 4] = o;
    }

    if (tid < 128) {
        float s = 0.f;
        for (int sidx = 0; sidx < 128; ++sidx) s += kfs[sidx * 128 + tid];
        g_ksum[(size_t)bx * 128 + tid] = s;
    }
}

// ---------------------------------------------------------------------------
// attention out (unchanged)
// ---------------------------------------------------------------------------
__global__ void __launch_bounds__(256) attn_k()
{
    extern __shared__ float sm[];
    float* qfs = sm;
    float* kvT = sm + 128 * 129;
    float* ks  = kvT + 128 * 64;

    const int bx = blockIdx.x;
    const int n = bx >> 3, h = bx & 7;
    const int tid = threadIdx.x;

    const float* qfg = g_qf + (size_t)bx * (Fdim * Mfeat);
    for (int idx = tid; idx < Fdim * Mfeat; idx += 256) {
        int l = idx >> 7, m = idx & 127;
        qfs[l * 129 + m] = qfg[idx];
    }
    const float* kvg = g_kv + (size_t)bx * (Edim * Mfeat);
    for (int idx = tid; idx < Edim * Mfeat; idx += 256) {
        int e = idx >> 7, m = idx & 127;
        kvT[m * 64 + e] = kvg[idx];
    }
    if (tid < 128) ks[tid] = g_ksum[(size_t)bx * 128 + tid];
    __syncthreads();

    const int ty = tid >> 4, tx = tid & 15;
    float acc[8][4];
    float den[8];
#pragma unroll
    for (int i = 0; i < 8; ++i) {
        den[i] = 0.f;
#pragma unroll
        for (int j = 0; j < 4; ++j) acc[i][j] = 0.f;
    }

    for (int m = 0; m < 128; ++m) {
        float br[4];
        *(float4*)br = *(const float4*)&kvT[m * 64 + tx * 4];
        float km = ks[m];
#pragma unroll
        for (int i = 0; i < 8; ++i) {
            float a = qfs[(ty * 8 + i) * 129 + m];
            den[i] += a * km;
#pragma unroll
            for (int j = 0; j < 4; ++j) acc[i][j] += a * br[j];
        }
    }

#pragma unroll
    for (int i = 0; i < 8; ++i) {
        int l = ty * 8 + i;
        float inv = 1.0f / (den[i] + ZEPS);
        float4 o = { acc[i][0] * inv, acc[i][1] * inv, acc[i][2] * inv, acc[i][3] * inv };
        *(float4*)&g_t[((size_t)l * Ndim + n) * MDL + h * Edim + tx * 4] = o;
    }
}

// ---------------------------------------------------------------------------
// AddNorm (unchanged)
// ---------------------------------------------------------------------------
__global__ void __launch_bounds__(128) addnorm_k(
    const float* __restrict__ a, const float* __restrict__ res,
    const float* __restrict__ g, const float* __restrict__ b,
    float* __restrict__ out)
{
    __shared__ float red[8];
    const int r = blockIdx.x, tid = threadIdx.x;
    const size_t base = (size_t)r * MDL + tid * 4;

    float4 va = *(const float4*)(a + base);
    float4 vr = *(const float4*)(res + base);
    float v[4] = { va.x + vr.x, va.y + vr.y, va.z + vr.z, va.w + vr.w };

    float s  = v[0] + v[1] + v[2] + v[3];
    float s2 = v[0]*v[0] + v[1]*v[1] + v[2]*v[2] + v[3]*v[3];
#pragma unroll
    for (int o = 16; o > 0; o >>= 1) {
        s  += __shfl_xor_sync(0xffffffffu, s,  o);
        s2 += __shfl_xor_sync(0xffffffffu, s2, o);
    }
    if ((tid & 31) == 0) { red[tid >> 5] = s; red[4 + (tid >> 5)] = s2; }
    __syncthreads();
    float ts  = red[0] + red[1] + red[2] + red[3];
    float ts2 = red[4] + red[5] + red[6] + red[7];
    float mean = ts * (1.0f / MDL);
    float var  = ts2 * (1.0f / MDL) - mean * mean;
    float rstd = rsqrtf(var + LNEPS);

    float4 gg = *(const float4*)(g + tid * 4);
    float4 bb = *(const float4*)(b + tid * 4);
    float4 o;
    o.x = (v[0] - mean) * rstd * gg.x + bb.x;
    o.y = (v[1] - mean) * rstd * gg.y + bb.y;
    o.z = (v[2] - mean) * rstd * gg.z + bb.z;
    o.w = (v[3] - mean) * rstd * gg.w + bb.w;
    *(float4*)(out + base) = o;
}

// ---------------------------------------------------------------------------
// Host launcher
// ---------------------------------------------------------------------------
extern "C" void kernel_launch(void* const* d_in, const int* in_sizes, int n_in,
                              void* d_out, int out_size)
{
    const float* x     = (const float*)d_in[0];
    const float* w_qkv = (const float*)d_in[1];
    const float* b_qkv = (const float*)d_in[2];
    const float* proj  = (const float*)d_in[3];
    const float* ln1_g = (const float*)d_in[4];
    const float* ln1_b = (const float*)d_in[5];
    const float* ln2_g = (const float*)d_in[6];
    const float* ln2_b = (const float*)d_in[7];
    const float* w1    = (const float*)d_in[8];
    const float* b1    = (const float*)d_in[9];
    const float* w2    = (const float*)d_in[10];
    const float* b2    = (const float*)d_in[11];
    float* out = (float*)d_out;

    float *p_qkv, *p_t, *p_x1, *p_h1, *p_y;
    cudaGetSymbolAddress((void**)&p_qkv, g_qkv);
    cudaGetSymbolAddress((void**)&p_t,   g_t);
    cudaGetSymbolAddress((void**)&p_x1,  g_x1);
    cudaGetSymbolAddress((void**)&p_h1,  g_h1);
    cudaGetSymbolAddress((void**)&p_y,   g_y);

    const int feat_smem = (128 * 65 + 64 * 128) * 4;
    const int kv_smem   = (128 * 65 + 128 * 128) * 4;
    const int attn_smem = (128 * 129 + 128 * 64 + 128) * 4;
    cudaFuncSetAttribute(feature_k, cudaFuncAttributeMaxDynamicSharedMemorySize, feat_smem);
    cudaFuncSetAttribute(kv_k,      cudaFuncAttributeMaxDynamicSharedMemorySize, kv_smem);
    cudaFuncSetAttribute(attn_k,    cudaFuncAttributeMaxDynamicSharedMemorySize, attn_smem);

    // 1) qkv = x @ w_qkv^T + b_qkv   [65536, 1536]  (tf32 tensor cores)
    tf32gemm<<<dim3(QKV_STRIDE / 128, ROWS / 128), 256>>>(
        x, w_qkv, b_qkv, p_qkv, ROWS, QKV_STRIDE, MDL, 0);

    // 2) FAVOR+ feature maps
    feature_k<<<2 * Ndim * HEADS, 256, feat_smem>>>(proj);

    // 3) kv + ksum
    kv_k<<<Ndim * HEADS, 256, kv_smem>>>();

    // 4) attention out
    attn_k<<<Ndim * HEADS, 256, attn_smem>>>();

    // 5) x1 = LN(t + x)
    addnorm_k<<<ROWS, 128>>>(p_t, x, ln1_g, ln1_b, p_x1);

    // 6) h1 = gelu(x1 @ w1^T + b1)   [65536, 256]  (tf32)
    tf32gemm<<<dim3(HID / 128, ROWS / 128), 256>>>(
        p_x1, w1, b1, p_h1, ROWS, HID, MDL, 1);

    // 7) y = h1 @ w2^T + b2          [65536, 512]  (tf32)
    tf32gemm<<<dim3(MDL / 128, ROWS / 128), 256>>>(
        p_h1, w2, b2, p_y, ROWS, MDL, HID, 0);

    // 8) out = LN(y + x1)
    addnorm_k<<<ROWS, 128>>>(p_y, p_x1, ln2_g, ln2_b, out);
}

// round 3
// speedup vs baseline: 2.9028x; 1.5942x over previous
#include <cuda_runtime.h>
#include <math.h>
#include <stdint.h>

// ---------------------------------------------------------------------------
// Problem constants
// ---------------------------------------------------------------------------
#define Fdim 128
#define Ndim 512
#define MDL  512
#define HEADS 8
#define Edim 64
#define Mfeat 128
#define HID 256
#define ROWS (Fdim * Ndim)          // 65536
#define QKV_STRIDE (3 * MDL)        // 1536
#define ROW_QKV ((size_t)Ndim * QKV_STRIDE)

#define DN 0.35355339059327373f      // 64^-0.25
#define RATIO 0.08838834764831845f   // 128^-0.5
#define KEPS 1e-4f
#define ZEPS 1e-6f
#define LNEPS 1e-5f

// ---------------------------------------------------------------------------
// Scratch (device globals — no allocation allowed)
// ---------------------------------------------------------------------------
__device__ float g_qkv[(size_t)ROWS * QKV_STRIDE];
__device__ float g_t[(size_t)ROWS * MDL];
__device__ float g_x1[(size_t)ROWS * MDL];
__device__ float g_h1[(size_t)ROWS * HID];
__device__ float g_y[(size_t)ROWS * MDL];

__device__ __forceinline__ uint32_t f2tf32(float f) {
    uint32_t u;
    asm("cvt.rna.tf32.f32 %0, %1;" : "=r"(u) : "f"(f));
    return u;
}

#define MMA_TF32(acc, a0, a1, a2, a3, b0, b1)                                 \
    asm volatile(                                                             \
        "mma.sync.aligned.m16n8k8.row.col.f32.tf32.tf32.f32 "                 \
        "{%0,%1,%2,%3}, {%4,%5,%6,%7}, {%8,%9}, {%0,%1,%2,%3};"               \
        : "+f"(acc[0]), "+f"(acc[1]), "+f"(acc[2]), "+f"(acc[3])              \
        : "r"(a0), "r"(a1), "r"(a2), "r"(a3), "r"(b0), "r"(b1))

// ---------------------------------------------------------------------------
// tf32 tensor-core GEMM: C[M,N] = A[M,K] @ B[N,K]^T + bias[N], optional GELU.
// (unchanged from R1)
// ---------------------------------------------------------------------------
__global__ void __launch_bounds__(256) tf32gemm(
    const float* __restrict__ A, const float* __restrict__ B,
    const float* __restrict__ bias, float* __restrict__ C,
    int M, int N, int K, int act)
{
    __shared__ uint32_t As[128][36];
    __shared__ uint32_t Bs[128][36];

    const int tid  = threadIdx.x;
    const int lane = tid & 31;
    const int w    = tid >> 5;
    const int warp_m = w & 1;
    const int warp_n = w >> 1;
    const int gid = lane >> 2;
    const int tig = lane & 3;

    const int bm = blockIdx.y, bn = blockIdx.x;
    const float* Ag = A + (size_t)bm * 128 * K;
    const float* Bg = B + (size_t)bn * 128 * K;

    const int lr = tid >> 3;
    const int lc = (tid & 7) * 4;

    float acc[4][4][4];
#pragma unroll
    for (int mt = 0; mt < 4; ++mt)
#pragma unroll
        for (int nt = 0; nt < 4; ++nt)
#pragma unroll
            for (int r = 0; r < 4; ++r) acc[mt][nt][r] = 0.f;

    for (int k0 = 0; k0 < K; k0 += 32) {
#pragma unroll
        for (int p = 0; p < 4; ++p) {
            int row = lr + p * 32;
            float4 av = *(const float4*)(Ag + (size_t)row * K + k0 + lc);
            float4 bv = *(const float4*)(Bg + (size_t)row * K + k0 + lc);
            As[row][lc + 0] = f2tf32(av.x); As[row][lc + 1] = f2tf32(av.y);
            As[row][lc + 2] = f2tf32(av.z); As[row][lc + 3] = f2tf32(av.w);
            Bs[row][lc + 0] = f2tf32(bv.x); Bs[row][lc + 1] = f2tf32(bv.y);
            Bs[row][lc + 2] = f2tf32(bv.z); Bs[row][lc + 3] = f2tf32(bv.w);
        }
        __syncthreads();

#pragma unroll
        for (int kk = 0; kk < 32; kk += 8) {
            uint32_t a[4][4], b[4][2];
#pragma unroll
            for (int mt = 0; mt < 4; ++mt) {
                int ar = warp_m * 64 + mt * 16 + gid;
                a[mt][0] = As[ar][kk + tig];
                a[mt][1] = As[ar + 8][kk + tig];
                a[mt][2] = As[ar][kk + tig + 4];
                a[mt][3] = As[ar + 8][kk + tig + 4];
            }
#pragma unroll
            for (int nt = 0; nt < 4; ++nt) {
                int br = warp_n * 32 + nt * 8 + gid;
                b[nt][0] = Bs[br][kk + tig];
                b[nt][1] = Bs[br][kk + tig + 4];
            }
#pragma unroll
            for (int mt = 0; mt < 4; ++mt)
#pragma unroll
                for (int nt = 0; nt < 4; ++nt)
                    MMA_TF32(acc[mt][nt], a[mt][0], a[mt][1], a[mt][2], a[mt][3],
                             b[nt][0], b[nt][1]);
        }
        __syncthreads();
    }

#pragma unroll
    for (int mt = 0; mt < 4; ++mt) {
        int row = bm * 128 + warp_m * 64 + mt * 16 + gid;
#pragma unroll
        for (int nt = 0; nt < 4; ++nt) {
            int col = bn * 128 + warp_n * 32 + nt * 8 + 2 * tig;
            float b0 = bias[col], b1 = bias[col + 1];
            float v0 = acc[mt][nt][0] + b0;
            float v1 = acc[mt][nt][1] + b1;
            float v2 = acc[mt][nt][2] + b0;
            float v3 = acc[mt][nt][3] + b1;
            if (act) {
                v0 = 0.5f * v0 * (1.0f + erff(v0 * 0.7071067811865476f));
                v1 = 0.5f * v1 * (1.0f + erff(v1 * 0.7071067811865476f));
                v2 = 0.5f * v2 * (1.0f + erff(v2 * 0.7071067811865476f));
                v3 = 0.5f * v3 * (1.0f + erff(v3 * 0.7071067811865476f));
            }
            *(float2*)(C + (size_t)row * N + col)       = make_float2(v0, v1);
            *(float2*)(C + (size_t)(row + 8) * N + col) = make_float2(v2, v3);
        }
    }
}

// ---------------------------------------------------------------------------
// Fused FAVOR+ attention per (n,h) block, all-tensor-core.
//   qf = featmap(q), kf = featmap(k)      (two 128x128x64 tf32 MMAs + exp)
//   P  = qf @ kf^T                        (128x128x128)
//   den[l] = sum_s P[l,s]                 (== qf @ ksum, re-associated)
//   t[l,e] = (P @ v)[l,e] / (den[l]+eps)  (128x64x128)
// Shared memory (word offsets):
//   QF  [128][132] tf32   0      (later overwritten by P)
//   KF  [128][132] tf32   16896
//   DB  [128][68]  tf32   33792  (q tile, then k tile, then vT[64][132])
//   PB  [128][68]  tf32   42496  (proj)
//   DS  [128] f32         51200  (row sum of squares)
//   DEN [128] f32         51328
// Total 51456 words = 205824 B. One block per SM.
// ---------------------------------------------------------------------------
__global__ void __launch_bounds__(256) fused_attn(const float* __restrict__ proj)
{
    extern __shared__ uint32_t smw[];
    uint32_t* QF = smw;
    uint32_t* KF = smw + 16896;
    uint32_t* DB = smw + 33792;
    uint32_t* PB = smw + 42496;
    float* DS  = (float*)(smw + 51200);
    float* DEN = (float*)(smw + 51328);

    const int bx = blockIdx.x;
    const int n = bx >> 3, h = bx & 7;
    const int tid  = threadIdx.x;
    const int lane = tid & 31, w = tid >> 5;
    const int gid = lane >> 2, tig = lane & 3;
    const int r0 = w * 16 + gid, r1 = r0 + 8;

    const size_t base_nh = (size_t)n * QKV_STRIDE + (size_t)h * Edim;

    // ---- load proj -> PB (tf32) ----
    {
        int m = tid >> 1, e0 = (tid & 1) * 32;
        const float* src = proj + m * 64 + e0;
#pragma unroll
        for (int j = 0; j < 8; ++j) {
            float4 v = *(const float4*)(src + j * 4);
            int o = m * 68 + e0 + j * 4;
            PB[o + 0] = f2tf32(v.x); PB[o + 1] = f2tf32(v.y);
            PB[o + 2] = f2tf32(v.z); PB[o + 3] = f2tf32(v.w);
        }
    }

    // ---- feature maps for q (sel=0) and k (sel=1) ----
    for (int sel = 0; sel < 2; ++sel) {
        // load data tile [128 x 64] -> DB, with fp32 row sum-of-squares
        {
            int r = tid >> 1, e0 = (tid & 1) * 32;
            const float* src = g_qkv + (size_t)r * ROW_QKV + base_nh
                               + (size_t)sel * MDL + e0;
            float sq = 0.f;
#pragma unroll
            for (int j = 0; j < 8; ++j) {
                float4 v = *(const float4*)(src + j * 4);
                sq += v.x * v.x + v.y * v.y + v.z * v.z + v.w * v.w;
                int o = r * 68 + e0 + j * 4;
                DB[o + 0] = f2tf32(v.x); DB[o + 1] = f2tf32(v.y);
                DB[o + 2] = f2tf32(v.z); DB[o + 3] = f2tf32(v.w);
            }
            sq += __shfl_xor_sync(0xffffffffu, sq, 1);
            if ((tid & 1) == 0) DS[r] = sq;
        }
        __syncthreads();

        // S = D @ proj^T  (warp tile 16x128, K=64)
        float acc[16][4];
#pragma unroll
        for (int nt = 0; nt < 16; ++nt)
#pragma unroll
            for (int r = 0; r < 4; ++r) acc[nt][r] = 0.f;

#pragma unroll
        for (int kk = 0; kk < 64; kk += 8) {
            uint32_t a0 = DB[r0 * 68 + kk + tig];
            uint32_t a1 = DB[r1 * 68 + kk + tig];
            uint32_t a2 = DB[r0 * 68 + kk + tig + 4];
            uint32_t a3 = DB[r1 * 68 + kk + tig + 4];
#pragma unroll
            for (int nt = 0; nt < 16; ++nt) {
                uint32_t b0 = PB[(nt * 8 + gid) * 68 + kk + tig];
                uint32_t b1 = PB[(nt * 8 + gid) * 68 + kk + tig + 4];
                MMA_TF32(acc[nt], a0, a1, a2, a3, b0, b1);
            }
        }

        // stabilizer (row max) + exp transform -> qf/kf
        float m0 = -1e30f, m1 = -1e30f;
#pragma unroll
        for (int nt = 0; nt < 16; ++nt) {
            m0 = fmaxf(m0, fmaxf(acc[nt][0], acc[nt][1]));
            m1 = fmaxf(m1, fmaxf(acc[nt][2], acc[nt][3]));
        }
        m0 = fmaxf(m0, __shfl_xor_sync(0xffffffffu, m0, 1));
        m0 = fmaxf(m0, __shfl_xor_sync(0xffffffffu, m0, 2));
        m1 = fmaxf(m1, __shfl_xor_sync(0xffffffffu, m1, 1));
        m1 = fmaxf(m1, __shfl_xor_sync(0xffffffffu, m1, 2));

        float c0 = -DS[r0] * (0.5f * DN * DN) - m0 * DN;
        float c1 = -DS[r1] * (0.5f * DN * DN) - m1 * DN;

        uint32_t* OUT = sel ? KF : QF;
#pragma unroll
        for (int nt = 0; nt < 16; ++nt) {
            int col = nt * 8 + 2 * tig;
            OUT[r0 * 132 + col]     = f2tf32(RATIO * (expf(acc[nt][0] * DN + c0) + KEPS));
            OUT[r0 * 132 + col + 1] = f2tf32(RATIO * (expf(acc[nt][1] * DN + c0) + KEPS));
            OUT[r1 * 132 + col]     = f2tf32(RATIO * (expf(acc[nt][2] * DN + c1) + KEPS));
            OUT[r1 * 132 + col + 1] = f2tf32(RATIO * (expf(acc[nt][3] * DN + c1) + KEPS));
        }
        __syncthreads();   // DB reads done; qf/kf visible
    }

    // ---- load v -> DB as vT[e][s] (tf32, stride 132) ----
    {
        int s = tid >> 1, e0 = (tid & 1) * 32;
        const float* src = g_qkv + (size_t)s * ROW_QKV + base_nh + 2 * MDL + e0;
#pragma unroll
        for (int j = 0; j < 8; ++j) {
            float4 v = *(const float4*)(src + j * 4);
            DB[(e0 + j * 4 + 0) * 132 + s] = f2tf32(v.x);
            DB[(e0 + j * 4 + 1) * 132 + s] = f2tf32(v.y);
            DB[(e0 + j * 4 + 2) * 132 + s] = f2tf32(v.z);
            DB[(e0 + j * 4 + 3) * 132 + s] = f2tf32(v.w);
        }
    }

    // ---- P = qf @ kf^T  (warp tile 16x128, K=128) ----
    float acc[16][4];
#pragma unroll
    for (int nt = 0; nt < 16; ++nt)
#pragma unroll
        for (int r = 0; r < 4; ++r) acc[nt][r] = 0.f;

#pragma unroll
    for (int kk = 0; kk < 128; kk += 8) {
        uint32_t a0 = QF[r0 * 132 + kk + tig];
        uint32_t a1 = QF[r1 * 132 + kk + tig];
        uint32_t a2 = QF[r0 * 132 + kk + tig + 4];
        uint32_t a3 = QF[r1 * 132 + kk + tig + 4];
#pragma unroll
        for (int nt = 0; nt < 16; ++nt) {
            uint32_t b0 = KF[(nt * 8 + gid) * 132 + kk + tig];
            uint32_t b1 = KF[(nt * 8 + gid) * 132 + kk + tig + 4];
            MMA_TF32(acc[nt], a0, a1, a2, a3, b0, b1);
        }
    }

    // den[l] = sum_s P[l,s]
    {
        float d0 = 0.f, d1 = 0.f;
#pragma unroll
        for (int nt = 0; nt < 16; ++nt) {
            d0 += acc[nt][0] + acc[nt][1];
            d1 += acc[nt][2] + acc[nt][3];
        }
        d0 += __shfl_xor_sync(0xffffffffu, d0, 1);
        d0 += __shfl_xor_sync(0xffffffffu, d0, 2);
        d1 += __shfl_xor_sync(0xffffffffu, d1, 1);
        d1 += __shfl_xor_sync(0xffffffffu, d1, 2);
        if (tig == 0) { DEN[r0] = d0; DEN[r1] = d1; }
    }
    __syncthreads();   // all P-MMA reads of QF complete

    // write P over QF (tf32)
#pragma unroll
    for (int nt = 0; nt < 16; ++nt) {
        int col = nt * 8 + 2 * tig;
        QF[r0 * 132 + col]     = f2tf32(acc[nt][0]);
        QF[r0 * 132 + col + 1] = f2tf32(acc[nt][1]);
        QF[r1 * 132 + col]     = f2tf32(acc[nt][2]);
        QF[r1 * 132 + col + 1] = f2tf32(acc[nt][3]);
    }
    __syncthreads();   // P + vT visible

    // ---- t = (P @ v) / den  (warp tile 16x64, K=128) ----
    float acc3[8][4];
#pragma unroll
    for (int nt = 0; nt < 8; ++nt)
#pragma unroll
        for (int r = 0; r < 4; ++r) acc3[nt][r] = 0.f;

#pragma unroll
    for (int kk = 0; kk < 128; kk += 8) {
        uint32_t a0 = QF[r0 * 132 + kk + tig];
        uint32_t a1 = QF[r1 * 132 + kk + tig];
        uint32_t a2 = QF[r0 * 132 + kk + tig + 4];
        uint32_t a3 = QF[r1 * 132 + kk + tig + 4];
#pragma unroll
        for (int nt = 0; nt < 8; ++nt) {
            uint32_t b0 = DB[(nt * 8 + gid) * 132 + kk + tig];
            uint32_t b1 = DB[(nt * 8 + gid) * 132 + kk + tig + 4];
            MMA_TF32(acc3[nt], a0, a1, a2, a3, b0, b1);
        }
    }

    const float inv0 = 1.0f / (DEN[r0] + ZEPS);
    const float inv1 = 1.0f / (DEN[r1] + ZEPS);
#pragma unroll
    for (int nt = 0; nt < 8; ++nt) {
        int col = nt * 8 + 2 * tig;     // e within head
        *(float2*)&g_t[((size_t)r0 * Ndim + n) * MDL + h * Edim + col] =
            make_float2(acc3[nt][0] * inv0, acc3[nt][1] * inv0);
        *(float2*)&g_t[((size_t)r1 * Ndim + n) * MDL + h * Edim + col] =
            make_float2(acc3[nt][2] * inv1, acc3[nt][3] * inv1);
    }
}

// ---------------------------------------------------------------------------
// AddNorm (unchanged)
// ---------------------------------------------------------------------------
__global__ void __launch_bounds__(128) addnorm_k(
    const float* __restrict__ a, const float* __restrict__ res,
    const float* __restrict__ g, const float* __restrict__ b,
    float* __restrict__ out)
{
    __shared__ float red[8];
    const int r = blockIdx.x, tid = threadIdx.x;
    const size_t base = (size_t)r * MDL + tid * 4;

    float4 va = *(const float4*)(a + base);
    float4 vr = *(const float4*)(res + base);
    float v[4] = { va.x + vr.x, va.y + vr.y, va.z + vr.z, va.w + vr.w };

    float s  = v[0] + v[1] + v[2] + v[3];
    float s2 = v[0]*v[0] + v[1]*v[1] + v[2]*v[2] + v[3]*v[3];
#pragma unroll
    for (int o = 16; o > 0; o >>= 1) {
        s  += __shfl_xor_sync(0xffffffffu, s,  o);
        s2 += __shfl_xor_sync(0xffffffffu, s2, o);
    }
    if ((tid & 31) == 0) { red[tid >> 5] = s; red[4 + (tid >> 5)] = s2; }
    __syncthreads();
    float ts  = red[0] + red[1] + red[2] + red[3];
    float ts2 = red[4] + red[5] + red[6] + red[7];
    float mean = ts * (1.0f / MDL);
    float var  = ts2 * (1.0f / MDL) - mean * mean;
    float rstd = rsqrtf(var + LNEPS);

    float4 gg = *(const float4*)(g + tid * 4);
    float4 bb = *(const float4*)(b + tid * 4);
    float4 o;
    o.x = (v[0] - mean) * rstd * gg.x + bb.x;
    o.y = (v[1] - mean) * rstd * gg.y + bb.y;
    o.z = (v[2] - mean) * rstd * gg.z + bb.z;
    o.w = (v[3] - mean) * rstd * gg.w + bb.w;
    *(float4*)(out + base) = o;
}

// ---------------------------------------------------------------------------
// Host launcher
// ---------------------------------------------------------------------------
extern "C" void kernel_launch(void* const* d_in, const int* in_sizes, int n_in,
                              void* d_out, int out_size)
{
    const float* x     = (const float*)d_in[0];
    const float* w_qkv = (const float*)d_in[1];
    const float* b_qkv = (const float*)d_in[2];
    const float* proj  = (const float*)d_in[3];
    const float* ln1_g = (const float*)d_in[4];
    const float* ln1_b = (const float*)d_in[5];
    const float* ln2_g = (const float*)d_in[6];
    const float* ln2_b = (const float*)d_in[7];
    const float* w1    = (const float*)d_in[8];
    const float* b1    = (const float*)d_in[9];
    const float* w2    = (const float*)d_in[10];
    const float* b2    = (const float*)d_in[11];
    float* out = (float*)d_out;

    float *p_qkv, *p_t, *p_x1, *p_h1, *p_y;
    cudaGetSymbolAddress((void**)&p_qkv, g_qkv);
    cudaGetSymbolAddress((void**)&p_t,   g_t);
    cudaGetSymbolAddress((void**)&p_x1,  g_x1);
    cudaGetSymbolAddress((void**)&p_h1,  g_h1);
    cudaGetSymbolAddress((void**)&p_y,   g_y);

    const int fused_smem = 51456 * 4;   // 205824 B
    cudaFuncSetAttribute(fused_attn, cudaFuncAttributeMaxDynamicSharedMemorySize,
                         fused_smem);

    // 1) qkv = x @ w_qkv^T + b_qkv   [65536, 1536]
    tf32gemm<<<dim3(QKV_STRIDE / 128, ROWS / 128), 256>>>(
        x, w_qkv, b_qkv, p_qkv, ROWS, QKV_STRIDE, MDL, 0);

    // 2-4) fused FAVOR+ attention -> g_t
    fused_attn<<<Ndim * HEADS, 256, fused_smem>>>(proj);

    // 5) x1 = LN(t + x)
    addnorm_k<<<ROWS, 128>>>(p_t, x, ln1_g, ln1_b, p_x1);

    // 6) h1 = gelu(x1 @ w1^T + b1)   [65536, 256]
    tf32gemm<<<dim3(HID / 128, ROWS / 128), 256>>>(
        p_x1, w1, b1, p_h1, ROWS, HID, MDL, 1);

    // 7) y = h1 @ w2^T + b2          [65536, 512]
    tf32gemm<<<dim3(MDL / 128, ROWS / 128), 256>>>(
        p_h1, w2, b2, p_y, ROWS, MDL, HID, 0);

    // 8) out = LN(y + x1)
    addnorm_k<<<ROWS, 128>>>(p_y, p_x1, ln2_g, ln2_b, out);
}